// round 2
// baseline (speedup 1.0000x reference)
#include <cuda_runtime.h>
#include <cuda_bf16.h>
#include <cstdint>

// Problem constants
#define BATCH 2
#define SEQ   2048
#define EMB   1024
#define HEADS 16
#define HDIM  64
#define C3    (3 * EMB)
#define MTOT  (BATCH * SEQ)   // 4096

// Scratch (allocation-free rule: __device__ globals)
__device__ float g_qkv[MTOT * C3];   // [4096, 3072]
__device__ float g_y[MTOT * EMB];    // [4096, 1024]

// ---------------------------------------------------------------------------
// NT GEMM: C[m,n] = sum_k A[m,k] * B[n,k] + bias[n]
// A: [M,K] row-major, B: [N,K] row-major. Tile 128x64, BK=16, 256 threads,
// 8x4 register micro-tile per thread.
// ---------------------------------------------------------------------------
__global__ __launch_bounds__(256) void gemm_nt_bias(
    const float* __restrict__ A, const float* __restrict__ Bm,
    const float* __restrict__ bias, float* __restrict__ C,
    int M, int N, int K)
{
    __shared__ float As[16][132];  // transposed A tile, padded (132*4B = 33*16B: float4-aligned rows)
    __shared__ float Bs[16][68];   // transposed B tile, padded (68*4B = 17*16B)

    const int t  = threadIdx.x;
    const int bm = blockIdx.y * 128;
    const int bn = blockIdx.x * 64;
    const int tx = t & 15;         // N split (4 cols each)
    const int ty = t >> 4;         // M split (8 rows each)

    const int ar = t >> 2;         // 0..63 (row within load slab)
    const int ak = (t & 3) << 2;   // k offset {0,4,8,12}

    const float* Aptr = A + (size_t)(bm + ar) * K + ak;
    const float* A2ptr = Aptr + (size_t)64 * K;
    const float* Bptr = Bm + (size_t)(bn + ar) * K + ak;

    float acc[8][4];
#pragma unroll
    for (int i = 0; i < 8; i++)
#pragma unroll
        for (int j = 0; j < 4; j++) acc[i][j] = 0.0f;

    for (int k0 = 0; k0 < K; k0 += 16) {
        float4 a0 = *(const float4*)(Aptr + k0);
        float4 a1 = *(const float4*)(A2ptr + k0);
        float4 b0 = *(const float4*)(Bptr + k0);

        As[ak + 0][ar] = a0.x; As[ak + 1][ar] = a0.y;
        As[ak + 2][ar] = a0.z; As[ak + 3][ar] = a0.w;
        As[ak + 0][ar + 64] = a1.x; As[ak + 1][ar + 64] = a1.y;
        As[ak + 2][ar + 64] = a1.z; As[ak + 3][ar + 64] = a1.w;
        Bs[ak + 0][ar] = b0.x; Bs[ak + 1][ar] = b0.y;
        Bs[ak + 2][ar] = b0.z; Bs[ak + 3][ar] = b0.w;
        __syncthreads();

#pragma unroll
        for (int kk = 0; kk < 16; kk++) {
            float a[8], b[4];
            *(float4*)(a)     = *(const float4*)(&As[kk][ty * 8]);
            *(float4*)(a + 4) = *(const float4*)(&As[kk][ty * 8 + 4]);
            *(float4*)(b)     = *(const float4*)(&Bs[kk][tx * 4]);
#pragma unroll
            for (int i = 0; i < 8; i++)
#pragma unroll
                for (int j = 0; j < 4; j++)
                    acc[i][j] = fmaf(a[i], b[j], acc[i][j]);
        }
        __syncthreads();
    }

    // epilogue: bias + coalesced float4 stores
    const float4 bb = *(const float4*)(bias + bn + tx * 4);
#pragma unroll
    for (int i = 0; i < 8; i++) {
        const int row = bm + ty * 8 + i;
        float4 v;
        v.x = acc[i][0] + bb.x;
        v.y = acc[i][1] + bb.y;
        v.z = acc[i][2] + bb.z;
        v.w = acc[i][3] + bb.w;
        *(float4*)(C + (size_t)row * N + bn + tx * 4) = v;
    }
}

// ---------------------------------------------------------------------------
// Flash attention, fp32. One block per (q-tile of 64 rows, head, batch).
// 256 threads: thread (r = t/4, c4 = t%4). Thread owns q-row r and a
// 16-wide column slice (k-columns for S, d-columns for O).
// Dynamic smem: Qs, Ks, Vs, Ps each [64][68] floats (row stride 272B: float4
// aligned, 17 16B-chunks/row -> bank spread).
// ---------------------------------------------------------------------------
__global__ __launch_bounds__(256) void attn_kernel(
    const float* __restrict__ qkv, float* __restrict__ y)
{
    extern __shared__ float sm[];
    float (*Qs)[68] = (float(*)[68])(sm);
    float (*Ks)[68] = (float(*)[68])(sm + 64 * 68);
    float (*Vs)[68] = (float(*)[68])(sm + 2 * 64 * 68);
    float (*Ps)[68] = (float(*)[68])(sm + 3 * 64 * 68);

    const int qt = blockIdx.x;   // 0..31
    const int h  = blockIdx.y;   // 0..15
    const int b  = blockIdx.z;   // 0..1

    const int t  = threadIdx.x;
    const int r  = t >> 2;       // q row in tile: 0..63
    const int c4 = t & 3;        // column quarter: 0..3

    const float scale = 0.125f;  // 1/sqrt(64)

    // Load Q tile: rows qt*64..+64, dims h*64..+64 (q part of qkv)
    const float* qbase = qkv + ((size_t)(b * SEQ + qt * 64)) * C3 + h * HDIM;
#pragma unroll
    for (int l = 0; l < 4; l++) {
        int idx = t + 256 * l;
        int row = idx >> 4;
        int ch  = idx & 15;
        *(float4*)(&Qs[row][ch * 4]) =
            *(const float4*)(qbase + (size_t)row * C3 + ch * 4);
    }

    float o[16];
#pragma unroll
    for (int i = 0; i < 16; i++) o[i] = 0.0f;
    float m_run = -1e30f;
    float l_run = 0.0f;

    const int qg = qt * 64 + r;  // global q row

    for (int j = 0; j <= qt; j++) {
        __syncthreads();  // prev PV done (and Q loaded on first iter)

        // Load K, V tiles (64 x 64)
        const float* kbase = qkv + ((size_t)(b * SEQ + j * 64)) * C3 + EMB + h * HDIM;
        const float* vbase = kbase + EMB;
#pragma unroll
        for (int l = 0; l < 4; l++) {
            int idx = t + 256 * l;
            int row = idx >> 4;
            int ch  = idx & 15;
            *(float4*)(&Ks[row][ch * 4]) =
                *(const float4*)(kbase + (size_t)row * C3 + ch * 4);
            *(float4*)(&Vs[row][ch * 4]) =
                *(const float4*)(vbase + (size_t)row * C3 + ch * 4);
        }
        __syncthreads();

        // S = Q K^T for this thread's 16 k-columns
        float s[16];
#pragma unroll
        for (int i = 0; i < 16; i++) s[i] = 0.0f;
#pragma unroll 4
        for (int d4 = 0; d4 < 16; d4++) {
            const float4 q = *(const float4*)(&Qs[r][d4 * 4]);
#pragma unroll
            for (int i = 0; i < 16; i++) {
                const float4 kk = *(const float4*)(&Ks[c4 * 16 + i][d4 * 4]);
                s[i] = fmaf(q.x, kk.x, s[i]);
                s[i] = fmaf(q.y, kk.y, s[i]);
                s[i] = fmaf(q.z, kk.z, s[i]);
                s[i] = fmaf(q.w, kk.w, s[i]);
            }
        }

        // scale + causal mask
        const int kg0 = j * 64 + c4 * 16;
#pragma unroll
        for (int i = 0; i < 16; i++) {
            s[i] *= scale;
            if (kg0 + i > qg) s[i] = -1e30f;
        }

        // online softmax: row max across 64 cols (16 local + shfl over 4 lanes)
        float mt = s[0];
#pragma unroll
        for (int i = 1; i < 16; i++) mt = fmaxf(mt, s[i]);
        mt = fmaxf(mt, __shfl_xor_sync(0xffffffffu, mt, 1));
        mt = fmaxf(mt, __shfl_xor_sync(0xffffffffu, mt, 2));

        const float m_new = fmaxf(m_run, mt);
        const float corr  = __expf(m_run - m_new);

        float ladd = 0.0f;
#pragma unroll
        for (int i = 0; i < 16; i++) {
            const float p = __expf(s[i] - m_new);
            s[i] = p;
            ladd += p;
        }
        ladd += __shfl_xor_sync(0xffffffffu, ladd, 1);
        ladd += __shfl_xor_sync(0xffffffffu, ladd, 2);

        l_run = l_run * corr + ladd;
        m_run = m_new;
#pragma unroll
        for (int i = 0; i < 16; i++) o[i] *= corr;

        // stage P
#pragma unroll
        for (int i = 0; i < 16; i++) Ps[r][c4 * 16 + i] = s[i];
        __syncthreads();

        // O += P V  (thread owns d-range c4*16..+16 of row r)
#pragma unroll 8
        for (int c = 0; c < 64; c++) {
            const float p = Ps[r][c];
#pragma unroll
            for (int jj = 0; jj < 4; jj++) {
                const float4 vv = *(const float4*)(&Vs[c][c4 * 16 + jj * 4]);
                o[jj * 4 + 0] = fmaf(p, vv.x, o[jj * 4 + 0]);
                o[jj * 4 + 1] = fmaf(p, vv.y, o[jj * 4 + 1]);
                o[jj * 4 + 2] = fmaf(p, vv.z, o[jj * 4 + 2]);
                o[jj * 4 + 3] = fmaf(p, vv.w, o[jj * 4 + 3]);
            }
        }
    }

    // epilogue: normalize and write y[b, t, h*64 + d]
    const float inv = 1.0f / l_run;
    float* ybase = y + ((size_t)(b * SEQ + qt * 64 + r)) * EMB + h * HDIM + c4 * 16;
#pragma unroll
    for (int jj = 0; jj < 4; jj++) {
        float4 v;
        v.x = o[jj * 4 + 0] * inv;
        v.y = o[jj * 4 + 1] * inv;
        v.z = o[jj * 4 + 2] * inv;
        v.w = o[jj * 4 + 3] * inv;
        *(float4*)(ybase + jj * 4) = v;
    }
}

// ---------------------------------------------------------------------------
// Launch
// ---------------------------------------------------------------------------
extern "C" void kernel_launch(void* const* d_in, const int* in_sizes, int n_in,
                              void* d_out, int out_size)
{
    const float* x      = (const float*)d_in[0];
    const float* w_attn = (const float*)d_in[1];
    const float* b_attn = (const float*)d_in[2];
    const float* w_proj = (const float*)d_in[3];
    const float* b_proj = (const float*)d_in[4];
    float* out = (float*)d_out;

    void* p;
    cudaGetSymbolAddress(&p, g_qkv);
    float* qkv = (float*)p;
    cudaGetSymbolAddress(&p, g_y);
    float* y = (float*)p;

    // 1) qkv = x @ w_attn^T + b_attn   [4096, 3072]
    {
        dim3 grid(C3 / 64, MTOT / 128);
        gemm_nt_bias<<<grid, 256>>>(x, w_attn, b_attn, qkv, MTOT, C3, EMB);
    }

    // 2) flash attention -> y [4096, 1024]
    {
        const int smem = 4 * 64 * 68 * (int)sizeof(float);  // 69632 B
        cudaFuncSetAttribute(attn_kernel,
                             cudaFuncAttributeMaxDynamicSharedMemorySize, smem);
        dim3 grid(SEQ / 64, HEADS, BATCH);
        attn_kernel<<<grid, 256, smem>>>(qkv, y);
    }

    // 3) out = y @ w_proj^T + b_proj   [4096, 1024]
    {
        dim3 grid(EMB / 64, MTOT / 128);
        gemm_nt_bias<<<grid, 256>>>(y, w_proj, b_proj, out, MTOT, EMB, EMB);
    }
}

// round 3
// speedup vs baseline: 1.0057x; 1.0057x over previous
#include <cuda_runtime.h>
#include <cuda_bf16.h>
#include <cstdint>

// Problem constants
#define BATCH 2
#define SEQ   2048
#define EMB   1024
#define HEADS 16
#define HDIM  64
#define C3    (3 * EMB)
#define MTOT  (BATCH * SEQ)   // 4096

// Scratch (allocation-free rule: __device__ globals)
__device__ float g_qkv[MTOT * C3];   // [4096, 3072]
__device__ float g_y[MTOT * EMB];    // [4096, 1024]

// ---------------------------------------------------------------------------
// NT GEMM: C[m,n] = sum_k A[m,k] * B[n,k] + bias[n]
// A: [M,K] row-major, B: [N,K] row-major. Tile 128x64, BK=16, 256 threads,
// 8x4 register micro-tile per thread.
// ---------------------------------------------------------------------------
__global__ __launch_bounds__(256) void gemm_nt_bias(
    const float* __restrict__ A, const float* __restrict__ Bm,
    const float* __restrict__ bias, float* __restrict__ C,
    int M, int N, int K)
{
    __shared__ float As[16][132];  // transposed A tile, padded (132*4B = 33*16B: float4-aligned rows)
    __shared__ float Bs[16][68];   // transposed B tile, padded (68*4B = 17*16B)

    const int t  = threadIdx.x;
    const int bm = blockIdx.y * 128;
    const int bn = blockIdx.x * 64;
    const int tx = t & 15;         // N split (4 cols each)
    const int ty = t >> 4;         // M split (8 rows each)

    const int ar = t >> 2;         // 0..63 (row within load slab)
    const int ak = (t & 3) << 2;   // k offset {0,4,8,12}

    const float* Aptr = A + (size_t)(bm + ar) * K + ak;
    const float* A2ptr = Aptr + (size_t)64 * K;
    const float* Bptr = Bm + (size_t)(bn + ar) * K + ak;

    float acc[8][4];
#pragma unroll
    for (int i = 0; i < 8; i++)
#pragma unroll
        for (int j = 0; j < 4; j++) acc[i][j] = 0.0f;

    for (int k0 = 0; k0 < K; k0 += 16) {
        float4 a0 = *(const float4*)(Aptr + k0);
        float4 a1 = *(const float4*)(A2ptr + k0);
        float4 b0 = *(const float4*)(Bptr + k0);

        As[ak + 0][ar] = a0.x; As[ak + 1][ar] = a0.y;
        As[ak + 2][ar] = a0.z; As[ak + 3][ar] = a0.w;
        As[ak + 0][ar + 64] = a1.x; As[ak + 1][ar + 64] = a1.y;
        As[ak + 2][ar + 64] = a1.z; As[ak + 3][ar + 64] = a1.w;
        Bs[ak + 0][ar] = b0.x; Bs[ak + 1][ar] = b0.y;
        Bs[ak + 2][ar] = b0.z; Bs[ak + 3][ar] = b0.w;
        __syncthreads();

#pragma unroll
        for (int kk = 0; kk < 16; kk++) {
            float a[8], b[4];
            *(float4*)(a)     = *(const float4*)(&As[kk][ty * 8]);
            *(float4*)(a + 4) = *(const float4*)(&As[kk][ty * 8 + 4]);
            *(float4*)(b)     = *(const float4*)(&Bs[kk][tx * 4]);
#pragma unroll
            for (int i = 0; i < 8; i++)
#pragma unroll
                for (int j = 0; j < 4; j++)
                    acc[i][j] = fmaf(a[i], b[j], acc[i][j]);
        }
        __syncthreads();
    }

    // epilogue: bias + coalesced float4 stores
    const float4 bb = *(const float4*)(bias + bn + tx * 4);
#pragma unroll
    for (int i = 0; i < 8; i++) {
        const int row = bm + ty * 8 + i;
        float4 v;
        v.x = acc[i][0] + bb.x;
        v.y = acc[i][1] + bb.y;
        v.z = acc[i][2] + bb.z;
        v.w = acc[i][3] + bb.w;
        *(float4*)(C + (size_t)row * N + bn + tx * 4) = v;
    }
}

// ---------------------------------------------------------------------------
// Flash attention, fp32. One block per (q-tile of 64 rows, head, batch).
// 256 threads: thread (r = t/4, c4 = t%4). Thread owns q-row r and a
// 16-wide column slice (k-columns for S, d-columns for O).
// Dynamic smem: Qs, Ks, Vs, Ps each [64][68] floats (row stride 272B: float4
// aligned, 17 16B-chunks/row -> bank spread).
// ---------------------------------------------------------------------------
__global__ __launch_bounds__(256) void attn_kernel(
    const float* __restrict__ qkv, float* __restrict__ y)
{
    extern __shared__ float sm[];
    float (*Qs)[68] = (float(*)[68])(sm);
    float (*Ks)[68] = (float(*)[68])(sm + 64 * 68);
    float (*Vs)[68] = (float(*)[68])(sm + 2 * 64 * 68);
    float (*Ps)[68] = (float(*)[68])(sm + 3 * 64 * 68);

    const int qt = blockIdx.x;   // 0..31
    const int h  = blockIdx.y;   // 0..15
    const int b  = blockIdx.z;   // 0..1

    const int t  = threadIdx.x;
    const int r  = t >> 2;       // q row in tile: 0..63
    const int c4 = t & 3;        // column quarter: 0..3

    const float scale = 0.125f;  // 1/sqrt(64)

    // Load Q tile: rows qt*64..+64, dims h*64..+64 (q part of qkv)
    const float* qbase = qkv + ((size_t)(b * SEQ + qt * 64)) * C3 + h * HDIM;
#pragma unroll
    for (int l = 0; l < 4; l++) {
        int idx = t + 256 * l;
        int row = idx >> 4;
        int ch  = idx & 15;
        *(float4*)(&Qs[row][ch * 4]) =
            *(const float4*)(qbase + (size_t)row * C3 + ch * 4);
    }

    float o[16];
#pragma unroll
    for (int i = 0; i < 16; i++) o[i] = 0.0f;
    float m_run = -1e30f;
    float l_run = 0.0f;

    const int qg = qt * 64 + r;  // global q row

    for (int j = 0; j <= qt; j++) {
        __syncthreads();  // prev PV done (and Q loaded on first iter)

        // Load K, V tiles (64 x 64)
        const float* kbase = qkv + ((size_t)(b * SEQ + j * 64)) * C3 + EMB + h * HDIM;
        const float* vbase = kbase + EMB;
#pragma unroll
        for (int l = 0; l < 4; l++) {
            int idx = t + 256 * l;
            int row = idx >> 4;
            int ch  = idx & 15;
            *(float4*)(&Ks[row][ch * 4]) =
                *(const float4*)(kbase + (size_t)row * C3 + ch * 4);
            *(float4*)(&Vs[row][ch * 4]) =
                *(const float4*)(vbase + (size_t)row * C3 + ch * 4);
        }
        __syncthreads();

        // S = Q K^T for this thread's 16 k-columns
        float s[16];
#pragma unroll
        for (int i = 0; i < 16; i++) s[i] = 0.0f;
#pragma unroll 4
        for (int d4 = 0; d4 < 16; d4++) {
            const float4 q = *(const float4*)(&Qs[r][d4 * 4]);
#pragma unroll
            for (int i = 0; i < 16; i++) {
                const float4 kk = *(const float4*)(&Ks[c4 * 16 + i][d4 * 4]);
                s[i] = fmaf(q.x, kk.x, s[i]);
                s[i] = fmaf(q.y, kk.y, s[i]);
                s[i] = fmaf(q.z, kk.z, s[i]);
                s[i] = fmaf(q.w, kk.w, s[i]);
            }
        }

        // scale + causal mask
        const int kg0 = j * 64 + c4 * 16;
#pragma unroll
        for (int i = 0; i < 16; i++) {
            s[i] *= scale;
            if (kg0 + i > qg) s[i] = -1e30f;
        }

        // online softmax: row max across 64 cols (16 local + shfl over 4 lanes)
        float mt = s[0];
#pragma unroll
        for (int i = 1; i < 16; i++) mt = fmaxf(mt, s[i]);
        mt = fmaxf(mt, __shfl_xor_sync(0xffffffffu, mt, 1));
        mt = fmaxf(mt, __shfl_xor_sync(0xffffffffu, mt, 2));

        const float m_new = fmaxf(m_run, mt);
        const float corr  = __expf(m_run - m_new);

        float ladd = 0.0f;
#pragma unroll
        for (int i = 0; i < 16; i++) {
            const float p = __expf(s[i] - m_new);
            s[i] = p;
            ladd += p;
        }
        ladd += __shfl_xor_sync(0xffffffffu, ladd, 1);
        ladd += __shfl_xor_sync(0xffffffffu, ladd, 2);

        l_run = l_run * corr + ladd;
        m_run = m_new;
#pragma unroll
        for (int i = 0; i < 16; i++) o[i] *= corr;

        // stage P
#pragma unroll
        for (int i = 0; i < 16; i++) Ps[r][c4 * 16 + i] = s[i];
        __syncthreads();

        // O += P V  (thread owns d-range c4*16..+16 of row r)
#pragma unroll 8
        for (int c = 0; c < 64; c++) {
            const float p = Ps[r][c];
#pragma unroll
            for (int jj = 0; jj < 4; jj++) {
                const float4 vv = *(const float4*)(&Vs[c][c4 * 16 + jj * 4]);
                o[jj * 4 + 0] = fmaf(p, vv.x, o[jj * 4 + 0]);
                o[jj * 4 + 1] = fmaf(p, vv.y, o[jj * 4 + 1]);
                o[jj * 4 + 2] = fmaf(p, vv.z, o[jj * 4 + 2]);
                o[jj * 4 + 3] = fmaf(p, vv.w, o[jj * 4 + 3]);
            }
        }
    }

    // epilogue: normalize and write y[b, t, h*64 + d]
    const float inv = 1.0f / l_run;
    float* ybase = y + ((size_t)(b * SEQ + qt * 64 + r)) * EMB + h * HDIM + c4 * 16;
#pragma unroll
    for (int jj = 0; jj < 4; jj++) {
        float4 v;
        v.x = o[jj * 4 + 0] * inv;
        v.y = o[jj * 4 + 1] * inv;
        v.z = o[jj * 4 + 2] * inv;
        v.w = o[jj * 4 + 3] * inv;
        *(float4*)(ybase + jj * 4) = v;
    }
}

// ---------------------------------------------------------------------------
// Launch
// ---------------------------------------------------------------------------
extern "C" void kernel_launch(void* const* d_in, const int* in_sizes, int n_in,
                              void* d_out, int out_size)
{
    const float* x      = (const float*)d_in[0];
    const float* w_attn = (const float*)d_in[1];
    const float* b_attn = (const float*)d_in[2];
    const float* w_proj = (const float*)d_in[3];
    const float* b_proj = (const float*)d_in[4];
    float* out = (float*)d_out;

    void* p;
    cudaGetSymbolAddress(&p, g_qkv);
    float* qkv = (float*)p;
    cudaGetSymbolAddress(&p, g_y);
    float* y = (float*)p;

    // 1) qkv = x @ w_attn^T + b_attn   [4096, 3072]
    {
        dim3 grid(C3 / 64, MTOT / 128);
        gemm_nt_bias<<<grid, 256>>>(x, w_attn, b_attn, qkv, MTOT, C3, EMB);
    }

    // 2) flash attention -> y [4096, 1024]
    {
        const int smem = 4 * 64 * 68 * (int)sizeof(float);  // 69632 B
        cudaFuncSetAttribute(attn_kernel,
                             cudaFuncAttributeMaxDynamicSharedMemorySize, smem);
        dim3 grid(SEQ / 64, HEADS, BATCH);
        attn_kernel<<<grid, 256, smem>>>(qkv, y);
    }

    // 3) out = y @ w_proj^T + b_proj   [4096, 1024]
    {
        dim3 grid(EMB / 64, MTOT / 128);
        gemm_nt_bias<<<grid, 256>>>(y, w_proj, b_proj, out, MTOT, EMB, EMB);
    }
}

// round 4
// speedup vs baseline: 3.3188x; 3.3001x over previous
#include <cuda_runtime.h>
#include <cuda_bf16.h>
#include <cstdint>

// Problem constants
#define BATCH 2
#define SEQ   2048
#define EMB   1024
#define HEADS 16
#define HDIM  64
#define C3    (3 * EMB)
#define MTOT  (BATCH * SEQ)   // 4096

// Scratch (allocation-free rule: __device__ globals)
__device__ float g_qkv[MTOT * C3];   // [4096, 3072]
__device__ float g_y[MTOT * EMB];    // [4096, 1024]

// ---------------------------------------------------------------------------
// NT GEMM: C[m,n] = sum_k A[m,k] * B[n,k] + bias[n]
// 128x128 tile, BK=8, 256 threads, 8x8 micro-tile as 2x2 blocks of 4x4.
// Double-buffered smem (one __syncthreads per k-tile), register prefetch.
// Smem rows padded to 132 floats: transposed scalar stores are conflict-free,
// row bases stay 16B-aligned.
// ---------------------------------------------------------------------------
__global__ __launch_bounds__(256, 2) void gemm_nt_bias(
    const float* __restrict__ A, const float* __restrict__ Bm,
    const float* __restrict__ bias, float* __restrict__ C,
    int M, int N, int K)
{
    __shared__ float As[2][8][132];
    __shared__ float Bs[2][8][132];

    const int t  = threadIdx.x;
    const int bm = blockIdx.y * 128;
    const int bn = blockIdx.x * 128;
    const int tx = t & 15;        // 0..15 -> cols tx*4 and tx*4+64
    const int ty = t >> 4;        // 0..15 -> rows ty*4 and ty*4+64

    // global load mapping: each thread loads one float4 of A and one of B
    const int lrow = t >> 1;          // 0..127
    const int lk   = (t & 1) * 4;     // 0 or 4

    const float* Ap = A + (size_t)(bm + lrow) * K + lk;
    const float* Bp = Bm + (size_t)(bn + lrow) * K + lk;

    float4 aR = *(const float4*)(Ap);
    float4 bR = *(const float4*)(Bp);

    As[0][lk + 0][lrow] = aR.x; As[0][lk + 1][lrow] = aR.y;
    As[0][lk + 2][lrow] = aR.z; As[0][lk + 3][lrow] = aR.w;
    Bs[0][lk + 0][lrow] = bR.x; Bs[0][lk + 1][lrow] = bR.y;
    Bs[0][lk + 2][lrow] = bR.z; Bs[0][lk + 3][lrow] = bR.w;
    __syncthreads();

    float acc[2][2][4][4];
#pragma unroll
    for (int p = 0; p < 2; p++)
#pragma unroll
        for (int q = 0; q < 2; q++)
#pragma unroll
            for (int i = 0; i < 4; i++)
#pragma unroll
                for (int j = 0; j < 4; j++) acc[p][q][i][j] = 0.0f;

    const int ntiles = K >> 3;
    int buf = 0;
    for (int kt = 0; kt < ntiles; kt++) {
        const bool has_next = (kt + 1) < ntiles;
        if (has_next) {
            aR = *(const float4*)(Ap + (kt + 1) * 8);
            bR = *(const float4*)(Bp + (kt + 1) * 8);
        }
#pragma unroll
        for (int kk = 0; kk < 8; kk++) {
            float a0[4], a1[4], b0[4], b1[4];
            *(float4*)a0 = *(const float4*)(&As[buf][kk][ty * 4]);
            *(float4*)a1 = *(const float4*)(&As[buf][kk][ty * 4 + 64]);
            *(float4*)b0 = *(const float4*)(&Bs[buf][kk][tx * 4]);
            *(float4*)b1 = *(const float4*)(&Bs[buf][kk][tx * 4 + 64]);
#pragma unroll
            for (int i = 0; i < 4; i++)
#pragma unroll
                for (int j = 0; j < 4; j++) {
                    acc[0][0][i][j] = fmaf(a0[i], b0[j], acc[0][0][i][j]);
                    acc[0][1][i][j] = fmaf(a0[i], b1[j], acc[0][1][i][j]);
                    acc[1][0][i][j] = fmaf(a1[i], b0[j], acc[1][0][i][j]);
                    acc[1][1][i][j] = fmaf(a1[i], b1[j], acc[1][1][i][j]);
                }
        }
        if (has_next) {
            buf ^= 1;
            As[buf][lk + 0][lrow] = aR.x; As[buf][lk + 1][lrow] = aR.y;
            As[buf][lk + 2][lrow] = aR.z; As[buf][lk + 3][lrow] = aR.w;
            Bs[buf][lk + 0][lrow] = bR.x; Bs[buf][lk + 1][lrow] = bR.y;
            Bs[buf][lk + 2][lrow] = bR.z; Bs[buf][lk + 3][lrow] = bR.w;
            __syncthreads();
        }
    }

    // epilogue: bias + coalesced float4 stores
#pragma unroll
    for (int p = 0; p < 2; p++)
#pragma unroll
        for (int q = 0; q < 2; q++) {
            const int rbase = bm + ty * 4 + p * 64;
            const int cbase = bn + tx * 4 + q * 64;
            const float4 bb = *(const float4*)(bias + cbase);
#pragma unroll
            for (int i = 0; i < 4; i++) {
                float4 v;
                v.x = acc[p][q][i][0] + bb.x;
                v.y = acc[p][q][i][1] + bb.y;
                v.z = acc[p][q][i][2] + bb.z;
                v.w = acc[p][q][i][3] + bb.w;
                *(float4*)(C + (size_t)(rbase + i) * N + cbase) = v;
            }
        }
}

// ---------------------------------------------------------------------------
// Flash attention, fp32, register-tiled. One block per (q-tile 64, head, b).
// 256 threads as 16x16: thread (ty = t/16, tx = t%16) owns a 4x4 micro-tile:
// q rows ty*4..+4, k cols (S phase) / d cols (PV phase) tx*4..+4.
// Q and K stored d-major (transposed) so the inner loops are outer products:
// all hot LDS are broadcasts or 256B-contiguous (conflict-free).
// Smem: QsT, KsT, Vs, Ps each [64][68] (row stride 272B, 16B-aligned).
// ---------------------------------------------------------------------------
__global__ __launch_bounds__(256, 2) void attn_kernel(
    const float* __restrict__ qkv, float* __restrict__ y)
{
    extern __shared__ float sm[];
    float (*QsT)[68] = (float(*)[68])(sm);                 // [d][r]
    float (*KsT)[68] = (float(*)[68])(sm + 64 * 68);       // [d][c]
    float (*Vs)[68]  = (float(*)[68])(sm + 2 * 64 * 68);   // [c][d]
    float (*Ps)[68]  = (float(*)[68])(sm + 3 * 64 * 68);   // [r][c]

    const int qt = gridDim.x - 1 - blockIdx.x;  // heaviest tiles first
    const int h  = blockIdx.y;
    const int b  = blockIdx.z;

    const int t  = threadIdx.x;
    const int tx = t & 15;
    const int ty = t >> 4;

    // Load Q tile transposed: QsT[d][r]
    const float* qbase = qkv + ((size_t)(b * SEQ + qt * 64)) * C3 + h * HDIM;
#pragma unroll
    for (int l = 0; l < 4; l++) {
        const int idx = t + 256 * l;
        const int row = idx >> 4;   // 0..63
        const int ch  = idx & 15;   // d chunk
        const float4 v = *(const float4*)(qbase + (size_t)row * C3 + ch * 4);
        QsT[ch * 4 + 0][row] = v.x;
        QsT[ch * 4 + 1][row] = v.y;
        QsT[ch * 4 + 2][row] = v.z;
        QsT[ch * 4 + 3][row] = v.w;
    }

    float o[4][4];
    float m_run[4], l_run[4];
#pragma unroll
    for (int i = 0; i < 4; i++) {
        m_run[i] = -1e30f;
        l_run[i] = 0.0f;
#pragma unroll
        for (int j = 0; j < 4; j++) o[i][j] = 0.0f;
    }

    const float scale = 0.125f;   // 1/sqrt(64)
    const int rowg = qt * 64 + ty * 4;

    for (int j = 0; j <= qt; j++) {
        __syncthreads();  // prev PV done reading Vs/Ps (and Q ready first iter)

        // Load K (transposed) and V (natural) tiles
        const float* kbase = qkv + ((size_t)(b * SEQ + j * 64)) * C3 + EMB + h * HDIM;
        const float* vbase = kbase + EMB;
#pragma unroll
        for (int l = 0; l < 4; l++) {
            const int idx = t + 256 * l;
            const int row = idx >> 4;
            const int ch  = idx & 15;
            const float4 kv = *(const float4*)(kbase + (size_t)row * C3 + ch * 4);
            KsT[ch * 4 + 0][row] = kv.x;
            KsT[ch * 4 + 1][row] = kv.y;
            KsT[ch * 4 + 2][row] = kv.z;
            KsT[ch * 4 + 3][row] = kv.w;
            *(float4*)(&Vs[row][ch * 4]) =
                *(const float4*)(vbase + (size_t)row * C3 + ch * 4);
        }
        __syncthreads();

        // S = Q K^T, 4x4 per thread (outer product over d)
        float s[4][4];
#pragma unroll
        for (int i = 0; i < 4; i++)
#pragma unroll
            for (int jj = 0; jj < 4; jj++) s[i][jj] = 0.0f;

#pragma unroll 8
        for (int d = 0; d < 64; d++) {
            float a[4], bb[4];
            *(float4*)a  = *(const float4*)(&QsT[d][ty * 4]);
            *(float4*)bb = *(const float4*)(&KsT[d][tx * 4]);
#pragma unroll
            for (int i = 0; i < 4; i++)
#pragma unroll
                for (int jj = 0; jj < 4; jj++)
                    s[i][jj] = fmaf(a[i], bb[jj], s[i][jj]);
        }

        // scale + causal mask + online softmax (row reduce over 16 tx lanes)
        const int colg = j * 64 + tx * 4;
#pragma unroll
        for (int i = 0; i < 4; i++) {
            float mt = -1e30f;
#pragma unroll
            for (int jj = 0; jj < 4; jj++) {
                float v = s[i][jj] * scale;
                v = (colg + jj <= rowg + i) ? v : -1e30f;
                s[i][jj] = v;
                mt = fmaxf(mt, v);
            }
            mt = fmaxf(mt, __shfl_xor_sync(0xffffffffu, mt, 1));
            mt = fmaxf(mt, __shfl_xor_sync(0xffffffffu, mt, 2));
            mt = fmaxf(mt, __shfl_xor_sync(0xffffffffu, mt, 4));
            mt = fmaxf(mt, __shfl_xor_sync(0xffffffffu, mt, 8));

            const float m_new = fmaxf(m_run[i], mt);
            const float corr  = __expf(m_run[i] - m_new);

            float ladd = 0.0f;
#pragma unroll
            for (int jj = 0; jj < 4; jj++) {
                const float p = __expf(s[i][jj] - m_new);
                s[i][jj] = p;
                ladd += p;
            }
            ladd += __shfl_xor_sync(0xffffffffu, ladd, 1);
            ladd += __shfl_xor_sync(0xffffffffu, ladd, 2);
            ladd += __shfl_xor_sync(0xffffffffu, ladd, 4);
            ladd += __shfl_xor_sync(0xffffffffu, ladd, 8);

            l_run[i] = l_run[i] * corr + ladd;
            m_run[i] = m_new;
#pragma unroll
            for (int jj = 0; jj < 4; jj++) o[i][jj] *= corr;
        }

        // stage P (float4 stores)
#pragma unroll
        for (int i = 0; i < 4; i++)
            *(float4*)(&Ps[ty * 4 + i][tx * 4]) =
                make_float4(s[i][0], s[i][1], s[i][2], s[i][3]);
        __syncthreads();

        // O += P V  (outer product over c, 4 cs per chunk)
#pragma unroll 4
        for (int c0 = 0; c0 < 64; c0 += 4) {
            float p4[4][4];
#pragma unroll
            for (int i = 0; i < 4; i++)
                *(float4*)p4[i] = *(const float4*)(&Ps[ty * 4 + i][c0]);
#pragma unroll
            for (int cc = 0; cc < 4; cc++) {
                float v4[4];
                *(float4*)v4 = *(const float4*)(&Vs[c0 + cc][tx * 4]);
#pragma unroll
                for (int i = 0; i < 4; i++)
#pragma unroll
                    for (int jj = 0; jj < 4; jj++)
                        o[i][jj] = fmaf(p4[i][cc], v4[jj], o[i][jj]);
            }
        }
    }

    // epilogue: normalize, write y[b, t, h*64 + d]
    float* ybase = y + ((size_t)(b * SEQ + qt * 64 + ty * 4)) * EMB + h * HDIM + tx * 4;
#pragma unroll
    for (int i = 0; i < 4; i++) {
        const float inv = 1.0f / l_run[i];
        float4 v;
        v.x = o[i][0] * inv;
        v.y = o[i][1] * inv;
        v.z = o[i][2] * inv;
        v.w = o[i][3] * inv;
        *(float4*)(ybase + (size_t)i * EMB) = v;
    }
}

// ---------------------------------------------------------------------------
// Launch
// ---------------------------------------------------------------------------
extern "C" void kernel_launch(void* const* d_in, const int* in_sizes, int n_in,
                              void* d_out, int out_size)
{
    const float* x      = (const float*)d_in[0];
    const float* w_attn = (const float*)d_in[1];
    const float* b_attn = (const float*)d_in[2];
    const float* w_proj = (const float*)d_in[3];
    const float* b_proj = (const float*)d_in[4];
    float* out = (float*)d_out;

    void* p;
    cudaGetSymbolAddress(&p, g_qkv);
    float* qkv = (float*)p;
    cudaGetSymbolAddress(&p, g_y);
    float* y = (float*)p;

    // 1) qkv = x @ w_attn^T + b_attn   [4096, 3072]
    {
        dim3 grid(C3 / 128, MTOT / 128);
        gemm_nt_bias<<<grid, 256>>>(x, w_attn, b_attn, qkv, MTOT, C3, EMB);
    }

    // 2) flash attention -> y [4096, 1024]
    {
        const int smem = 4 * 64 * 68 * (int)sizeof(float);  // 69632 B
        cudaFuncSetAttribute(attn_kernel,
                             cudaFuncAttributeMaxDynamicSharedMemorySize, smem);
        dim3 grid(SEQ / 64, HEADS, BATCH);
        attn_kernel<<<grid, 256, smem>>>(qkv, y);
    }

    // 3) out = y @ w_proj^T + b_proj   [4096, 1024]
    {
        dim3 grid(EMB / 128, MTOT / 128);
        gemm_nt_bias<<<grid, 256>>>(y, w_proj, b_proj, out, MTOT, EMB, EMB);
    }
}

// round 6
// speedup vs baseline: 4.9452x; 1.4900x over previous
#include <cuda_runtime.h>
#include <cuda_bf16.h>
#include <cstdint>

// Problem constants
#define BATCH 2
#define SEQ   2048
#define EMB   1024
#define HEADS 16
#define HDIM  64
#define C3    (3 * EMB)
#define MTOT  (BATCH * SEQ)   // 4096

// Scratch (allocation-free rule: __device__ globals)
__device__ float g_qkv[MTOT * C3];   // [4096, 3072] fp32
__device__ float g_y[MTOT * EMB];    // [4096, 1024] fp32
// split-bf16 operand copies (hi/lo)
__device__ __nv_bfloat16 g_x_h[MTOT * EMB];
__device__ __nv_bfloat16 g_x_l[MTOT * EMB];
__device__ __nv_bfloat16 g_wa_h[C3 * EMB];
__device__ __nv_bfloat16 g_wa_l[C3 * EMB];
__device__ __nv_bfloat16 g_wp_h[EMB * EMB];
__device__ __nv_bfloat16 g_wp_l[EMB * EMB];
__device__ __nv_bfloat16 g_y_h[MTOT * EMB];
__device__ __nv_bfloat16 g_y_l[MTOT * EMB];

// ---------------------------------------------------------------------------
// helpers (all plain sm_80-level PTX: valid at compute_103)
// ---------------------------------------------------------------------------
__device__ __forceinline__ uint32_t smem_u32(const void* p) {
    uint32_t a;
    asm("{ .reg .u64 t; cvta.to.shared.u64 t, %1; cvt.u32.u64 %0, t; }"
        : "=r"(a) : "l"(p));
    return a;
}

__device__ __forceinline__ void cpasync16(uint32_t dst, const void* src) {
    asm volatile("cp.async.cg.shared.global [%0], [%1], 16;"
                 :: "r"(dst), "l"(src) : "memory");
}
#define CP_COMMIT() asm volatile("cp.async.commit_group;" ::: "memory")

__device__ __forceinline__ void ldsm4(uint32_t* r, uint32_t addr) {
    asm volatile("ldmatrix.sync.aligned.m8n8.x4.shared.b16 {%0,%1,%2,%3}, [%4];"
                 : "=r"(r[0]), "=r"(r[1]), "=r"(r[2]), "=r"(r[3]) : "r"(addr));
}

__device__ __forceinline__ void mma16816(float* c, const uint32_t* a,
                                         uint32_t b0, uint32_t b1) {
    asm volatile(
        "mma.sync.aligned.m16n8k16.row.col.f32.bf16.bf16.f32 "
        "{%0,%1,%2,%3}, {%4,%5,%6,%7}, {%8,%9}, {%0,%1,%2,%3};"
        : "+f"(c[0]), "+f"(c[1]), "+f"(c[2]), "+f"(c[3])
        : "r"(a[0]), "r"(a[1]), "r"(a[2]), "r"(a[3]), "r"(b0), "r"(b1));
}

#define SWZ(o) ((o) ^ (((o) >> 3) & 0x70))

// ---------------------------------------------------------------------------
// split fp32 -> (hi, lo) bf16
// ---------------------------------------------------------------------------
__global__ __launch_bounds__(256) void split_kernel(
    const float4* __restrict__ in, uint2* __restrict__ hi,
    uint2* __restrict__ lo, int n4)
{
    const int i = blockIdx.x * 256 + threadIdx.x;
    if (i >= n4) return;
    const float4 v = in[i];
    __nv_bfloat162 h0 = __floats2bfloat162_rn(v.x, v.y);
    __nv_bfloat162 h1 = __floats2bfloat162_rn(v.z, v.w);
    const float2 f0 = __bfloat1622float2(h0);
    const float2 f1 = __bfloat1622float2(h1);
    __nv_bfloat162 l0 = __floats2bfloat162_rn(v.x - f0.x, v.y - f0.y);
    __nv_bfloat162 l1 = __floats2bfloat162_rn(v.z - f1.x, v.w - f1.y);
    hi[i] = make_uint2(*(uint32_t*)&h0, *(uint32_t*)&h1);
    lo[i] = make_uint2(*(uint32_t*)&l0, *(uint32_t*)&l1);
}

// ---------------------------------------------------------------------------
// HMMA NT GEMM: C[m,n] = sum_k A[m,k]*B[n,k] + bias[n]; A,B pre-split bf16.
// CTA 128x128, 8 warps (2x4), warp tile 64x32. BK=64 chunk (128B rows, SW128).
// cp.async double-buffered; 3-pass split accumulate Ah*Bh + Ah*Bl + Al*Bh.
// smem: 2 stages x 4 tiles (Ah,Al,Bh,Bl) x 16KB = 128KB (+ align pad).
// ---------------------------------------------------------------------------
#define TILE_B  16384
#define STAGE_B (4 * TILE_B)
#define GSMEM   (2 * STAGE_B + 1024)

__global__ __launch_bounds__(256, 1) void gemm_hmma(
    const __nv_bfloat16* __restrict__ Ah, const __nv_bfloat16* __restrict__ Al,
    const __nv_bfloat16* __restrict__ Bh, const __nv_bfloat16* __restrict__ Bl,
    const float* __restrict__ bias, float* __restrict__ C,
    int M, int N, int K)
{
    extern __shared__ char smr[];
    const uint32_t sb = (smem_u32(smr) + 1023u) & ~1023u;

    const int t    = threadIdx.x;
    const int lane = t & 31;
    const int wid  = t >> 5;
    const int warp_m = wid & 1;     // 0..1  (64 rows each)
    const int warp_n = wid >> 1;    // 0..3  (32 cols each)
    const int bm = blockIdx.y * 128;
    const int bn = blockIdx.x * 128;

    // lane-derived ldmatrix row mappings
    const int lg = lane >> 3, lr = lane & 7;
    const int a_mloc = (lg & 1) * 8 + lr;  const int a_kh = lg >> 1;
    const int b_nloc = (lg >> 1) * 8 + lr; const int b_kh = lg & 1;

    const int NC = K >> 6;   // chunks of 64

    // ---- cp.async fill of one chunk into a stage ----
    auto issue = [&](int kt, int stage) {
        const uint32_t base = sb + stage * STAGE_B;
        const int k0 = kt << 6;
#pragma unroll
        for (int l = 0; l < 4; l++) {
            const int idx = t + 256 * l;
            const int row = idx >> 3;    // 0..127
            const int ch  = idx & 7;     // 16B chunk in 128B row
            const uint32_t off = (uint32_t)(row * 128 + ch * 16);
            const uint32_t sw  = SWZ(off);
            const size_t ga = (size_t)(bm + row) * K + k0 + ch * 8;
            const size_t gb = (size_t)(bn + row) * K + k0 + ch * 8;
            cpasync16(base + sw,              Ah + ga);
            cpasync16(base + TILE_B + sw,     Al + ga);
            cpasync16(base + 2 * TILE_B + sw, Bh + gb);
            cpasync16(base + 3 * TILE_B + sw, Bl + gb);
        }
    };

    float acc[4][4][4];
#pragma unroll
    for (int i = 0; i < 4; i++)
#pragma unroll
        for (int j = 0; j < 4; j++)
#pragma unroll
            for (int e = 0; e < 4; e++) acc[i][j][e] = 0.0f;

    issue(0, 0);
    CP_COMMIT();

    for (int kt = 0; kt < NC; kt++) {
        if (kt + 1 < NC) {
            issue(kt + 1, (kt + 1) & 1);
            CP_COMMIT();
            asm volatile("cp.async.wait_group 1;" ::: "memory");
        } else {
            asm volatile("cp.async.wait_group 0;" ::: "memory");
        }
        __syncthreads();

        const uint32_t base = sb + (kt & 1) * STAGE_B;
#pragma unroll
        for (int ks = 0; ks < 4; ks++) {
            uint32_t ah[4][4], al[4][4], bh[2][4], bl[2][4];
#pragma unroll
            for (int mt = 0; mt < 4; mt++) {
                const int row = warp_m * 64 + mt * 16 + a_mloc;
                const uint32_t off = (uint32_t)(row * 128 + ks * 32 + a_kh * 16);
                const uint32_t sw = SWZ(off);
                ldsm4(ah[mt], base + sw);
                ldsm4(al[mt], base + TILE_B + sw);
            }
#pragma unroll
            for (int np = 0; np < 2; np++) {
                const int row = warp_n * 32 + np * 16 + b_nloc;
                const uint32_t off = (uint32_t)(row * 128 + ks * 32 + b_kh * 16);
                const uint32_t sw = SWZ(off);
                ldsm4(bh[np], base + 2 * TILE_B + sw);
                ldsm4(bl[np], base + 3 * TILE_B + sw);
            }
            // pass 1: Ah*Bh
#pragma unroll
            for (int mt = 0; mt < 4; mt++)
#pragma unroll
                for (int nt = 0; nt < 4; nt++)
                    mma16816(acc[mt][nt], ah[mt],
                             bh[nt >> 1][(nt & 1) * 2], bh[nt >> 1][(nt & 1) * 2 + 1]);
            // pass 2: Ah*Bl
#pragma unroll
            for (int mt = 0; mt < 4; mt++)
#pragma unroll
                for (int nt = 0; nt < 4; nt++)
                    mma16816(acc[mt][nt], ah[mt],
                             bl[nt >> 1][(nt & 1) * 2], bl[nt >> 1][(nt & 1) * 2 + 1]);
            // pass 3: Al*Bh
#pragma unroll
            for (int mt = 0; mt < 4; mt++)
#pragma unroll
                for (int nt = 0; nt < 4; nt++)
                    mma16816(acc[mt][nt], al[mt],
                             bh[nt >> 1][(nt & 1) * 2], bh[nt >> 1][(nt & 1) * 2 + 1]);
        }
        __syncthreads();
    }

    // epilogue: bias + float2 stores (m16n8 C frag layout)
#pragma unroll
    for (int mt = 0; mt < 4; mt++) {
        const int row = bm + warp_m * 64 + mt * 16 + (lane >> 2);
#pragma unroll
        for (int nt = 0; nt < 4; nt++) {
            const int col = bn + warp_n * 32 + nt * 8 + (lane & 3) * 2;
            const float2 bb = *(const float2*)(bias + col);
            float2 v0, v1;
            v0.x = acc[mt][nt][0] + bb.x;
            v0.y = acc[mt][nt][1] + bb.y;
            v1.x = acc[mt][nt][2] + bb.x;
            v1.y = acc[mt][nt][3] + bb.y;
            *(float2*)(C + (size_t)row * N + col) = v0;
            *(float2*)(C + (size_t)(row + 8) * N + col) = v1;
        }
    }
}

// ---------------------------------------------------------------------------
// Flash attention, fp32, register-tiled (unchanged from round 4, proven).
// ---------------------------------------------------------------------------
__global__ __launch_bounds__(256, 2) void attn_kernel(
    const float* __restrict__ qkv, float* __restrict__ y)
{
    extern __shared__ float sm[];
    float (*QsT)[68] = (float(*)[68])(sm);
    float (*KsT)[68] = (float(*)[68])(sm + 64 * 68);
    float (*Vs)[68]  = (float(*)[68])(sm + 2 * 64 * 68);
    float (*Ps)[68]  = (float(*)[68])(sm + 3 * 64 * 68);

    const int qt = gridDim.x - 1 - blockIdx.x;
    const int h  = blockIdx.y;
    const int b  = blockIdx.z;

    const int t  = threadIdx.x;
    const int tx = t & 15;
    const int ty = t >> 4;

    const float* qbase = qkv + ((size_t)(b * SEQ + qt * 64)) * C3 + h * HDIM;
#pragma unroll
    for (int l = 0; l < 4; l++) {
        const int idx = t + 256 * l;
        const int row = idx >> 4;
        const int ch  = idx & 15;
        const float4 v = *(const float4*)(qbase + (size_t)row * C3 + ch * 4);
        QsT[ch * 4 + 0][row] = v.x;
        QsT[ch * 4 + 1][row] = v.y;
        QsT[ch * 4 + 2][row] = v.z;
        QsT[ch * 4 + 3][row] = v.w;
    }

    float o[4][4];
    float m_run[4], l_run[4];
#pragma unroll
    for (int i = 0; i < 4; i++) {
        m_run[i] = -1e30f;
        l_run[i] = 0.0f;
#pragma unroll
        for (int j = 0; j < 4; j++) o[i][j] = 0.0f;
    }

    const float scale = 0.125f;
    const int rowg = qt * 64 + ty * 4;

    for (int j = 0; j <= qt; j++) {
        __syncthreads();

        const float* kbase = qkv + ((size_t)(b * SEQ + j * 64)) * C3 + EMB + h * HDIM;
        const float* vbase = kbase + EMB;
#pragma unroll
        for (int l = 0; l < 4; l++) {
            const int idx = t + 256 * l;
            const int row = idx >> 4;
            const int ch  = idx & 15;
            const float4 kv = *(const float4*)(kbase + (size_t)row * C3 + ch * 4);
            KsT[ch * 4 + 0][row] = kv.x;
            KsT[ch * 4 + 1][row] = kv.y;
            KsT[ch * 4 + 2][row] = kv.z;
            KsT[ch * 4 + 3][row] = kv.w;
            *(float4*)(&Vs[row][ch * 4]) =
                *(const float4*)(vbase + (size_t)row * C3 + ch * 4);
        }
        __syncthreads();

        float s[4][4];
#pragma unroll
        for (int i = 0; i < 4; i++)
#pragma unroll
            for (int jj = 0; jj < 4; jj++) s[i][jj] = 0.0f;

#pragma unroll 8
        for (int d = 0; d < 64; d++) {
            float a[4], bb[4];
            *(float4*)a  = *(const float4*)(&QsT[d][ty * 4]);
            *(float4*)bb = *(const float4*)(&KsT[d][tx * 4]);
#pragma unroll
            for (int i = 0; i < 4; i++)
#pragma unroll
                for (int jj = 0; jj < 4; jj++)
                    s[i][jj] = fmaf(a[i], bb[jj], s[i][jj]);
        }

        const int colg = j * 64 + tx * 4;
#pragma unroll
        for (int i = 0; i < 4; i++) {
            float mt = -1e30f;
#pragma unroll
            for (int jj = 0; jj < 4; jj++) {
                float v = s[i][jj] * scale;
                v = (colg + jj <= rowg + i) ? v : -1e30f;
                s[i][jj] = v;
                mt = fmaxf(mt, v);
            }
            mt = fmaxf(mt, __shfl_xor_sync(0xffffffffu, mt, 1));
            mt = fmaxf(mt, __shfl_xor_sync(0xffffffffu, mt, 2));
            mt = fmaxf(mt, __shfl_xor_sync(0xffffffffu, mt, 4));
            mt = fmaxf(mt, __shfl_xor_sync(0xffffffffu, mt, 8));

            const float m_new = fmaxf(m_run[i], mt);
            const float corr  = __expf(m_run[i] - m_new);

            float ladd = 0.0f;
#pragma unroll
            for (int jj = 0; jj < 4; jj++) {
                const float p = __expf(s[i][jj] - m_new);
                s[i][jj] = p;
                ladd += p;
            }
            ladd += __shfl_xor_sync(0xffffffffu, ladd, 1);
            ladd += __shfl_xor_sync(0xffffffffu, ladd, 2);
            ladd += __shfl_xor_sync(0xffffffffu, ladd, 4);
            ladd += __shfl_xor_sync(0xffffffffu, ladd, 8);

            l_run[i] = l_run[i] * corr + ladd;
            m_run[i] = m_new;
#pragma unroll
            for (int jj = 0; jj < 4; jj++) o[i][jj] *= corr;
        }

#pragma unroll
        for (int i = 0; i < 4; i++)
            *(float4*)(&Ps[ty * 4 + i][tx * 4]) =
                make_float4(s[i][0], s[i][1], s[i][2], s[i][3]);
        __syncthreads();

#pragma unroll 4
        for (int c0 = 0; c0 < 64; c0 += 4) {
            float p4[4][4];
#pragma unroll
            for (int i = 0; i < 4; i++)
                *(float4*)p4[i] = *(const float4*)(&Ps[ty * 4 + i][c0]);
#pragma unroll
            for (int cc = 0; cc < 4; cc++) {
                float v4[4];
                *(float4*)v4 = *(const float4*)(&Vs[c0 + cc][tx * 4]);
#pragma unroll
                for (int i = 0; i < 4; i++)
#pragma unroll
                    for (int jj = 0; jj < 4; jj++)
                        o[i][jj] = fmaf(p4[i][cc], v4[jj], o[i][jj]);
            }
        }
    }

    float* ybase = y + ((size_t)(b * SEQ + qt * 64 + ty * 4)) * EMB + h * HDIM + tx * 4;
#pragma unroll
    for (int i = 0; i < 4; i++) {
        const float inv = 1.0f / l_run[i];
        float4 v;
        v.x = o[i][0] * inv;
        v.y = o[i][1] * inv;
        v.z = o[i][2] * inv;
        v.w = o[i][3] * inv;
        *(float4*)(ybase + (size_t)i * EMB) = v;
    }
}

// ---------------------------------------------------------------------------
// Launch
// ---------------------------------------------------------------------------
extern "C" void kernel_launch(void* const* d_in, const int* in_sizes, int n_in,
                              void* d_out, int out_size)
{
    const float* x      = (const float*)d_in[0];
    const float* w_attn = (const float*)d_in[1];
    const float* b_attn = (const float*)d_in[2];
    const float* w_proj = (const float*)d_in[3];
    const float* b_proj = (const float*)d_in[4];
    float* out = (float*)d_out;

    void* p;
    cudaGetSymbolAddress(&p, g_qkv);   float* qkv = (float*)p;
    cudaGetSymbolAddress(&p, g_y);     float* y   = (float*)p;
    cudaGetSymbolAddress(&p, g_x_h);   __nv_bfloat16* x_h  = (__nv_bfloat16*)p;
    cudaGetSymbolAddress(&p, g_x_l);   __nv_bfloat16* x_l  = (__nv_bfloat16*)p;
    cudaGetSymbolAddress(&p, g_wa_h);  __nv_bfloat16* wa_h = (__nv_bfloat16*)p;
    cudaGetSymbolAddress(&p, g_wa_l);  __nv_bfloat16* wa_l = (__nv_bfloat16*)p;
    cudaGetSymbolAddress(&p, g_wp_h);  __nv_bfloat16* wp_h = (__nv_bfloat16*)p;
    cudaGetSymbolAddress(&p, g_wp_l);  __nv_bfloat16* wp_l = (__nv_bfloat16*)p;
    cudaGetSymbolAddress(&p, g_y_h);   __nv_bfloat16* y_h  = (__nv_bfloat16*)p;
    cudaGetSymbolAddress(&p, g_y_l);   __nv_bfloat16* y_l  = (__nv_bfloat16*)p;

    cudaFuncSetAttribute(gemm_hmma,
                         cudaFuncAttributeMaxDynamicSharedMemorySize, GSMEM);

    // 0) split inputs to (hi, lo) bf16
    {
        int n4 = MTOT * EMB / 4;
        split_kernel<<<n4 / 256, 256>>>((const float4*)x, (uint2*)x_h, (uint2*)x_l, n4);
        n4 = C3 * EMB / 4;
        split_kernel<<<n4 / 256, 256>>>((const float4*)w_attn, (uint2*)wa_h, (uint2*)wa_l, n4);
        n4 = EMB * EMB / 4;
        split_kernel<<<n4 / 256, 256>>>((const float4*)w_proj, (uint2*)wp_h, (uint2*)wp_l, n4);
    }

    // 1) qkv = x @ w_attn^T + b_attn   [4096, 3072]
    {
        dim3 grid(C3 / 128, MTOT / 128);
        gemm_hmma<<<grid, 256, GSMEM>>>(x_h, x_l, wa_h, wa_l, b_attn, qkv,
                                        MTOT, C3, EMB);
    }

    // 2) flash attention -> y [4096, 1024]
    {
        const int smem = 4 * 64 * 68 * (int)sizeof(float);
        cudaFuncSetAttribute(attn_kernel,
                             cudaFuncAttributeMaxDynamicSharedMemorySize, smem);
        dim3 grid(SEQ / 64, HEADS, BATCH);
        attn_kernel<<<grid, 256, smem>>>(qkv, y);
    }

    // 3) split y, then out = y @ w_proj^T + b_proj   [4096, 1024]
    {
        int n4 = MTOT * EMB / 4;
        split_kernel<<<n4 / 256, 256>>>((const float4*)y, (uint2*)y_h, (uint2*)y_l, n4);
        dim3 grid(EMB / 128, MTOT / 128);
        gemm_hmma<<<grid, 256, GSMEM>>>(y_h, y_l, wp_h, wp_l, b_proj, out,
                                        MTOT, EMB, EMB);
    }
}

// round 7
// speedup vs baseline: 9.1790x; 1.8561x over previous
#include <cuda_runtime.h>
#include <cuda_bf16.h>
#include <cstdint>

// Problem constants
#define BATCH 2
#define SEQ   2048
#define EMB   1024
#define HEADS 16
#define HDIM  64
#define C3    (3 * EMB)
#define MTOT  (BATCH * SEQ)   // 4096

// Scratch (allocation-free rule: __device__ globals)
__device__ __nv_bfloat16 g_x_h[MTOT * EMB];
__device__ __nv_bfloat16 g_x_l[MTOT * EMB];
__device__ __nv_bfloat16 g_wa_h[C3 * EMB];
__device__ __nv_bfloat16 g_wa_l[C3 * EMB];
__device__ __nv_bfloat16 g_wp_h[EMB * EMB];
__device__ __nv_bfloat16 g_wp_l[EMB * EMB];
__device__ __nv_bfloat16 g_qkv_h[MTOT * C3];   // split qkv (written by GEMM)
__device__ __nv_bfloat16 g_qkv_l[MTOT * C3];
__device__ __nv_bfloat16 g_y_h[MTOT * EMB];    // split attn output
__device__ __nv_bfloat16 g_y_l[MTOT * EMB];

// ---------------------------------------------------------------------------
// helpers (plain sm_80-level PTX: valid at compute_103)
// ---------------------------------------------------------------------------
__device__ __forceinline__ uint32_t smem_u32(const void* p) {
    uint32_t a;
    asm("{ .reg .u64 t; cvta.to.shared.u64 t, %1; cvt.u32.u64 %0, t; }"
        : "=r"(a) : "l"(p));
    return a;
}

__device__ __forceinline__ void cpasync16(uint32_t dst, const void* src) {
    asm volatile("cp.async.cg.shared.global [%0], [%1], 16;"
                 :: "r"(dst), "l"(src) : "memory");
}
#define CP_COMMIT() asm volatile("cp.async.commit_group;" ::: "memory")

__device__ __forceinline__ void ldsm4(uint32_t* r, uint32_t addr) {
    asm volatile("ldmatrix.sync.aligned.m8n8.x4.shared.b16 {%0,%1,%2,%3}, [%4];"
                 : "=r"(r[0]), "=r"(r[1]), "=r"(r[2]), "=r"(r[3]) : "r"(addr));
}
__device__ __forceinline__ void ldsm4t(uint32_t* r, uint32_t addr) {
    asm volatile("ldmatrix.sync.aligned.m8n8.x4.trans.shared.b16 {%0,%1,%2,%3}, [%4];"
                 : "=r"(r[0]), "=r"(r[1]), "=r"(r[2]), "=r"(r[3]) : "r"(addr));
}

__device__ __forceinline__ void mma16816(float* c, const uint32_t* a,
                                         uint32_t b0, uint32_t b1) {
    asm volatile(
        "mma.sync.aligned.m16n8k16.row.col.f32.bf16.bf16.f32 "
        "{%0,%1,%2,%3}, {%4,%5,%6,%7}, {%8,%9}, {%0,%1,%2,%3};"
        : "+f"(c[0]), "+f"(c[1]), "+f"(c[2]), "+f"(c[3])
        : "r"(a[0]), "r"(a[1]), "r"(a[2]), "r"(a[3]), "r"(b0), "r"(b1));
}

#define SWZ(o) ((o) ^ (((o) >> 3) & 0x70))

// fp32 pair -> packed bf16x2 hi (return) + lo (out param)
__device__ __forceinline__ uint32_t pack_split(float x, float y, uint32_t& lo) {
    __nv_bfloat162 h = __floats2bfloat162_rn(x, y);
    const float2 f = __bfloat1622float2(h);
    __nv_bfloat162 l = __floats2bfloat162_rn(x - f.x, y - f.y);
    lo = *(uint32_t*)&l;
    return *(uint32_t*)&h;
}

// ---------------------------------------------------------------------------
// split fp32 -> (hi, lo) bf16
// ---------------------------------------------------------------------------
__global__ __launch_bounds__(256) void split_kernel(
    const float4* __restrict__ in, uint2* __restrict__ hi,
    uint2* __restrict__ lo, int n4)
{
    const int i = blockIdx.x * 256 + threadIdx.x;
    if (i >= n4) return;
    const float4 v = in[i];
    __nv_bfloat162 h0 = __floats2bfloat162_rn(v.x, v.y);
    __nv_bfloat162 h1 = __floats2bfloat162_rn(v.z, v.w);
    const float2 f0 = __bfloat1622float2(h0);
    const float2 f1 = __bfloat1622float2(h1);
    __nv_bfloat162 l0 = __floats2bfloat162_rn(v.x - f0.x, v.y - f0.y);
    __nv_bfloat162 l1 = __floats2bfloat162_rn(v.z - f1.x, v.w - f1.y);
    hi[i] = make_uint2(*(uint32_t*)&h0, *(uint32_t*)&h1);
    lo[i] = make_uint2(*(uint32_t*)&l0, *(uint32_t*)&l1);
}

// ---------------------------------------------------------------------------
// HMMA NT GEMM: C = A @ B^T + bias (A,B pre-split bf16). 3-pass split accum.
// SPLIT_OUT: write split bf16 (Ch/Cl) instead of fp32 C.
// ---------------------------------------------------------------------------
#define TILE_B  16384
#define STAGE_B (4 * TILE_B)
#define GSMEM   (2 * STAGE_B + 1024)

template<bool SPLIT_OUT>
__global__ __launch_bounds__(256, 1) void gemm_hmma(
    const __nv_bfloat16* __restrict__ Ah, const __nv_bfloat16* __restrict__ Al,
    const __nv_bfloat16* __restrict__ Bh, const __nv_bfloat16* __restrict__ Bl,
    const float* __restrict__ bias, float* __restrict__ C,
    __nv_bfloat16* __restrict__ Ch, __nv_bfloat16* __restrict__ Cl,
    int M, int N, int K)
{
    extern __shared__ char smr[];
    const uint32_t sb = (smem_u32(smr) + 1023u) & ~1023u;

    const int t    = threadIdx.x;
    const int lane = t & 31;
    const int wid  = t >> 5;
    const int warp_m = wid & 1;
    const int warp_n = wid >> 1;
    const int bm = blockIdx.y * 128;
    const int bn = blockIdx.x * 128;

    const int lg = lane >> 3, lr = lane & 7;
    const int a_mloc = (lg & 1) * 8 + lr;  const int a_kh = lg >> 1;
    const int b_nloc = (lg >> 1) * 8 + lr; const int b_kh = lg & 1;

    const int NC = K >> 6;

    auto issue = [&](int kt, int stage) {
        const uint32_t base = sb + stage * STAGE_B;
        const int k0 = kt << 6;
#pragma unroll
        for (int l = 0; l < 4; l++) {
            const int idx = t + 256 * l;
            const int row = idx >> 3;
            const int ch  = idx & 7;
            const uint32_t sw = SWZ((uint32_t)(row * 128 + ch * 16));
            const size_t ga = (size_t)(bm + row) * K + k0 + ch * 8;
            const size_t gb = (size_t)(bn + row) * K + k0 + ch * 8;
            cpasync16(base + sw,              Ah + ga);
            cpasync16(base + TILE_B + sw,     Al + ga);
            cpasync16(base + 2 * TILE_B + sw, Bh + gb);
            cpasync16(base + 3 * TILE_B + sw, Bl + gb);
        }
    };

    float acc[4][4][4];
#pragma unroll
    for (int i = 0; i < 4; i++)
#pragma unroll
        for (int j = 0; j < 4; j++)
#pragma unroll
            for (int e = 0; e < 4; e++) acc[i][j][e] = 0.0f;

    issue(0, 0);
    CP_COMMIT();

    for (int kt = 0; kt < NC; kt++) {
        if (kt + 1 < NC) {
            issue(kt + 1, (kt + 1) & 1);
            CP_COMMIT();
            asm volatile("cp.async.wait_group 1;" ::: "memory");
        } else {
            asm volatile("cp.async.wait_group 0;" ::: "memory");
        }
        __syncthreads();

        const uint32_t base = sb + (kt & 1) * STAGE_B;
#pragma unroll
        for (int ks = 0; ks < 4; ks++) {
            uint32_t ah[4][4], al[4][4], bh[2][4], bl[2][4];
#pragma unroll
            for (int mt = 0; mt < 4; mt++) {
                const int row = warp_m * 64 + mt * 16 + a_mloc;
                const uint32_t sw = SWZ((uint32_t)(row * 128 + ks * 32 + a_kh * 16));
                ldsm4(ah[mt], base + sw);
                ldsm4(al[mt], base + TILE_B + sw);
            }
#pragma unroll
            for (int np = 0; np < 2; np++) {
                const int row = warp_n * 32 + np * 16 + b_nloc;
                const uint32_t sw = SWZ((uint32_t)(row * 128 + ks * 32 + b_kh * 16));
                ldsm4(bh[np], base + 2 * TILE_B + sw);
                ldsm4(bl[np], base + 3 * TILE_B + sw);
            }
#pragma unroll
            for (int mt = 0; mt < 4; mt++)
#pragma unroll
                for (int nt = 0; nt < 4; nt++)
                    mma16816(acc[mt][nt], ah[mt],
                             bh[nt >> 1][(nt & 1) * 2], bh[nt >> 1][(nt & 1) * 2 + 1]);
#pragma unroll
            for (int mt = 0; mt < 4; mt++)
#pragma unroll
                for (int nt = 0; nt < 4; nt++)
                    mma16816(acc[mt][nt], ah[mt],
                             bl[nt >> 1][(nt & 1) * 2], bl[nt >> 1][(nt & 1) * 2 + 1]);
#pragma unroll
            for (int mt = 0; mt < 4; mt++)
#pragma unroll
                for (int nt = 0; nt < 4; nt++)
                    mma16816(acc[mt][nt], al[mt],
                             bh[nt >> 1][(nt & 1) * 2], bh[nt >> 1][(nt & 1) * 2 + 1]);
        }
        __syncthreads();
    }

#pragma unroll
    for (int mt = 0; mt < 4; mt++) {
        const int row = bm + warp_m * 64 + mt * 16 + (lane >> 2);
#pragma unroll
        for (int nt = 0; nt < 4; nt++) {
            const int col = bn + warp_n * 32 + nt * 8 + (lane & 3) * 2;
            const float2 bb = *(const float2*)(bias + col);
            const float c00 = acc[mt][nt][0] + bb.x;
            const float c01 = acc[mt][nt][1] + bb.y;
            const float c10 = acc[mt][nt][2] + bb.x;
            const float c11 = acc[mt][nt][3] + bb.y;
            if (SPLIT_OUT) {
                uint32_t lo0, lo1;
                const uint32_t hi0 = pack_split(c00, c01, lo0);
                const uint32_t hi1 = pack_split(c10, c11, lo1);
                *(uint32_t*)(Ch + (size_t)row * N + col)       = hi0;
                *(uint32_t*)(Cl + (size_t)row * N + col)       = lo0;
                *(uint32_t*)(Ch + (size_t)(row + 8) * N + col) = hi1;
                *(uint32_t*)(Cl + (size_t)(row + 8) * N + col) = lo1;
            } else {
                *(float2*)(C + (size_t)row * N + col)       = make_float2(c00, c01);
                *(float2*)(C + (size_t)(row + 8) * N + col) = make_float2(c10, c11);
            }
        }
    }
}

// ---------------------------------------------------------------------------
// HMMA flash attention. CTA: 128 q-rows x (head, batch). 8 warps x 16 rows.
// k-blocks of 64, cp.async double-buffered (Kh,Kl,Vh,Vl each 64x64 bf16).
// S = QK^T via 3-pass split HMMA; softmax fp32 in C-frag registers;
// P re-split to bf16; PV via 3-pass HMMA with FA2 C->A frag identity and
// ldmatrix.trans for V. Output written as split bf16 (y_h, y_l).
// ---------------------------------------------------------------------------
#define KTILE_B   8192           // 64 rows * 128 B
#define ASTAGE_B  (4 * KTILE_B)  // 32 KB
#define ASMEM     (32768 + 2 * ASTAGE_B + 1024)

__global__ __launch_bounds__(256, 1) void attn_hmma(
    const __nv_bfloat16* __restrict__ Gh, const __nv_bfloat16* __restrict__ Gl,
    __nv_bfloat16* __restrict__ Yh, __nv_bfloat16* __restrict__ Yl)
{
    extern __shared__ char smr[];
    const uint32_t sb  = (smem_u32(smr) + 1023u) & ~1023u;
    const uint32_t sQh = sb;
    const uint32_t sQl = sb + 16384;
    const uint32_t sKV = sb + 32768;

    const int t = threadIdx.x;
    const int lane = t & 31, wid = t >> 5;
    const int lg = lane >> 3, lr = lane & 7;
    const int a_mloc = (lg & 1) * 8 + lr, a_kh = lg >> 1;
    const int b_nloc = (lg >> 1) * 8 + lr, b_kh = lg & 1;

    const int qt = gridDim.x - 1 - blockIdx.x;   // heaviest first
    const int h  = blockIdx.y;
    const int b  = blockIdx.z;

    const size_t qrow0 = (size_t)b * SEQ + qt * 128;
    const size_t hoff  = (size_t)h * HDIM;

    // prologue: Q tiles (group 0)
#pragma unroll
    for (int l = 0; l < 4; l++) {
        const int idx = t + 256 * l;
        const int row = idx >> 3, ch = idx & 7;
        const uint32_t sw = SWZ((uint32_t)(row * 128 + ch * 16));
        const size_t g = (qrow0 + row) * C3 + hoff + ch * 8;
        cpasync16(sQh + sw, Gh + g);
        cpasync16(sQl + sw, Gl + g);
    }
    CP_COMMIT();

    auto fill = [&](int kb, int st) {
        const uint32_t base = sKV + st * ASTAGE_B;
#pragma unroll
        for (int l = 0; l < 2; l++) {
            const int idx = t + 256 * l;
            const int row = idx >> 3, ch = idx & 7;
            const uint32_t sw = SWZ((uint32_t)(row * 128 + ch * 16));
            const size_t g = ((size_t)b * SEQ + kb * 64 + row) * C3 + hoff + ch * 8;
            cpasync16(base + sw,               Gh + g + EMB);       // Kh
            cpasync16(base + KTILE_B + sw,     Gl + g + EMB);       // Kl
            cpasync16(base + 2 * KTILE_B + sw, Gh + g + 2 * EMB);   // Vh
            cpasync16(base + 3 * KTILE_B + sw, Gl + g + 2 * EMB);   // Vl
        }
    };
    fill(0, 0);
    CP_COMMIT();
    asm volatile("cp.async.wait_group 0;" ::: "memory");
    __syncthreads();

    // Q fragments (kept in registers for the whole CTA)
    uint32_t qh[4][4], ql[4][4];
#pragma unroll
    for (int ks = 0; ks < 4; ks++) {
        const int row = wid * 16 + a_mloc;
        const uint32_t sw = SWZ((uint32_t)(row * 128 + ks * 32 + a_kh * 16));
        ldsm4(qh[ks], sQh + sw);
        ldsm4(ql[ks], sQl + sw);
    }

    float of[8][4];
#pragma unroll
    for (int i = 0; i < 8; i++)
#pragma unroll
        for (int e = 0; e < 4; e++) of[i][e] = 0.0f;
    float m_run[2] = {-1e30f, -1e30f};
    float l_run[2] = {0.0f, 0.0f};

    const int nkb = 2 * qt + 2;
    for (int kb = 0; kb < nkb; kb++) {
        if (kb + 1 < nkb) {
            fill(kb + 1, (kb + 1) & 1);
            CP_COMMIT();
            asm volatile("cp.async.wait_group 1;" ::: "memory");
        } else {
            asm volatile("cp.async.wait_group 0;" ::: "memory");
        }
        __syncthreads();

        const uint32_t kbase = sKV + (kb & 1) * ASTAGE_B;

        // ---- S = Q K^T (3 passes) ----
        float sf[8][4];
#pragma unroll
        for (int i = 0; i < 8; i++)
#pragma unroll
            for (int e = 0; e < 4; e++) sf[i][e] = 0.0f;

#pragma unroll
        for (int ks = 0; ks < 4; ks++) {
            uint32_t kh4[4][4], kl4[4][4];
#pragma unroll
            for (int g = 0; g < 4; g++) {
                const int row = g * 16 + b_nloc;
                const uint32_t sw = SWZ((uint32_t)(row * 128 + ks * 32 + b_kh * 16));
                ldsm4(kh4[g], kbase + sw);
                ldsm4(kl4[g], kbase + KTILE_B + sw);
            }
#pragma unroll
            for (int nt = 0; nt < 8; nt++)
                mma16816(sf[nt], qh[ks], kh4[nt >> 1][(nt & 1) * 2],
                         kh4[nt >> 1][(nt & 1) * 2 + 1]);
#pragma unroll
            for (int nt = 0; nt < 8; nt++)
                mma16816(sf[nt], qh[ks], kl4[nt >> 1][(nt & 1) * 2],
                         kl4[nt >> 1][(nt & 1) * 2 + 1]);
#pragma unroll
            for (int nt = 0; nt < 8; nt++)
                mma16816(sf[nt], ql[ks], kh4[nt >> 1][(nt & 1) * 2],
                         kh4[nt >> 1][(nt & 1) * 2 + 1]);
        }

        // ---- online softmax (rows lane>>2 and +8 within warp tile) ----
        const bool diag = (kb >= 2 * qt);
#pragma unroll
        for (int half = 0; half < 2; half++) {
            const int rowg = qt * 128 + wid * 16 + (lane >> 2) + half * 8;
            float mx = -1e30f;
#pragma unroll
            for (int nt = 0; nt < 8; nt++)
#pragma unroll
                for (int e = 0; e < 2; e++) {
                    float v = sf[nt][half * 2 + e] * 0.125f;
                    if (diag) {
                        const int colg = kb * 64 + nt * 8 + (lane & 3) * 2 + e;
                        if (colg > rowg) v = -1e30f;
                    }
                    sf[nt][half * 2 + e] = v;
                    mx = fmaxf(mx, v);
                }
            mx = fmaxf(mx, __shfl_xor_sync(0xffffffffu, mx, 1));
            mx = fmaxf(mx, __shfl_xor_sync(0xffffffffu, mx, 2));
            const float m_new = fmaxf(m_run[half], mx);
            const float corr  = __expf(m_run[half] - m_new);
            float ls = 0.0f;
#pragma unroll
            for (int nt = 0; nt < 8; nt++)
#pragma unroll
                for (int e = 0; e < 2; e++) {
                    const float p = __expf(sf[nt][half * 2 + e] - m_new);
                    sf[nt][half * 2 + e] = p;
                    ls += p;
                }
            l_run[half] = l_run[half] * corr + ls;   // lane-partial sum
            m_run[half] = m_new;
#pragma unroll
            for (int dt = 0; dt < 8; dt++) {
                of[dt][half * 2]     *= corr;
                of[dt][half * 2 + 1] *= corr;
            }
        }

        // ---- O += P V (3 passes), P via FA2 C->A identity ----
        const uint32_t vbase = kbase + 2 * KTILE_B;
#pragma unroll
        for (int kc = 0; kc < 4; kc++) {
            uint32_t pa_h[4], pa_l[4];
            pa_h[0] = pack_split(sf[kc * 2][0],     sf[kc * 2][1],     pa_l[0]);
            pa_h[1] = pack_split(sf[kc * 2][2],     sf[kc * 2][3],     pa_l[1]);
            pa_h[2] = pack_split(sf[kc * 2 + 1][0], sf[kc * 2 + 1][1], pa_l[2]);
            pa_h[3] = pack_split(sf[kc * 2 + 1][2], sf[kc * 2 + 1][3], pa_l[3]);

            uint32_t vh4[4][4], vl4[4][4];
#pragma unroll
            for (int dc = 0; dc < 4; dc++) {
                const int krow = kc * 16 + (lg & 1) * 8 + lr;
                const uint32_t sw =
                    SWZ((uint32_t)(krow * 128 + (dc * 16 + (lg >> 1) * 8) * 2));
                ldsm4t(vh4[dc], vbase + sw);
                ldsm4t(vl4[dc], vbase + KTILE_B + sw);
            }
#pragma unroll
            for (int dt = 0; dt < 8; dt++)
                mma16816(of[dt], pa_h, vh4[dt >> 1][(dt & 1) * 2],
                         vh4[dt >> 1][(dt & 1) * 2 + 1]);
#pragma unroll
            for (int dt = 0; dt < 8; dt++)
                mma16816(of[dt], pa_h, vl4[dt >> 1][(dt & 1) * 2],
                         vl4[dt >> 1][(dt & 1) * 2 + 1]);
#pragma unroll
            for (int dt = 0; dt < 8; dt++)
                mma16816(of[dt], pa_l, vh4[dt >> 1][(dt & 1) * 2],
                         vh4[dt >> 1][(dt & 1) * 2 + 1]);
        }
        __syncthreads();
    }

    // ---- epilogue: finish l reduction, normalize, write split bf16 ----
    float inv[2];
#pragma unroll
    for (int half = 0; half < 2; half++) {
        float l = l_run[half];
        l += __shfl_xor_sync(0xffffffffu, l, 1);
        l += __shfl_xor_sync(0xffffffffu, l, 2);
        inv[half] = 1.0f / l;
    }
    const size_t orow = qrow0 + wid * 16 + (lane >> 2);
    const size_t obase = orow * EMB + hoff + (lane & 3) * 2;
#pragma unroll
    for (int dt = 0; dt < 8; dt++) {
        uint32_t lo0, lo1;
        const uint32_t hi0 =
            pack_split(of[dt][0] * inv[0], of[dt][1] * inv[0], lo0);
        const uint32_t hi1 =
            pack_split(of[dt][2] * inv[1], of[dt][3] * inv[1], lo1);
        *(uint32_t*)(Yh + obase + dt * 8)           = hi0;
        *(uint32_t*)(Yl + obase + dt * 8)           = lo0;
        *(uint32_t*)(Yh + obase + 8 * EMB + dt * 8) = hi1;
        *(uint32_t*)(Yl + obase + 8 * EMB + dt * 8) = lo1;
    }
}

// ---------------------------------------------------------------------------
// Launch
// ---------------------------------------------------------------------------
extern "C" void kernel_launch(void* const* d_in, const int* in_sizes, int n_in,
                              void* d_out, int out_size)
{
    const float* x      = (const float*)d_in[0];
    const float* w_attn = (const float*)d_in[1];
    const float* b_attn = (const float*)d_in[2];
    const float* w_proj = (const float*)d_in[3];
    const float* b_proj = (const float*)d_in[4];
    float* out = (float*)d_out;

    void* p;
    cudaGetSymbolAddress(&p, g_x_h);    __nv_bfloat16* x_h   = (__nv_bfloat16*)p;
    cudaGetSymbolAddress(&p, g_x_l);    __nv_bfloat16* x_l   = (__nv_bfloat16*)p;
    cudaGetSymbolAddress(&p, g_wa_h);   __nv_bfloat16* wa_h  = (__nv_bfloat16*)p;
    cudaGetSymbolAddress(&p, g_wa_l);   __nv_bfloat16* wa_l  = (__nv_bfloat16*)p;
    cudaGetSymbolAddress(&p, g_wp_h);   __nv_bfloat16* wp_h  = (__nv_bfloat16*)p;
    cudaGetSymbolAddress(&p, g_wp_l);   __nv_bfloat16* wp_l  = (__nv_bfloat16*)p;
    cudaGetSymbolAddress(&p, g_qkv_h);  __nv_bfloat16* qkv_h = (__nv_bfloat16*)p;
    cudaGetSymbolAddress(&p, g_qkv_l);  __nv_bfloat16* qkv_l = (__nv_bfloat16*)p;
    cudaGetSymbolAddress(&p, g_y_h);    __nv_bfloat16* y_h   = (__nv_bfloat16*)p;
    cudaGetSymbolAddress(&p, g_y_l);    __nv_bfloat16* y_l   = (__nv_bfloat16*)p;

    cudaFuncSetAttribute(gemm_hmma<true>,
                         cudaFuncAttributeMaxDynamicSharedMemorySize, GSMEM);
    cudaFuncSetAttribute(gemm_hmma<false>,
                         cudaFuncAttributeMaxDynamicSharedMemorySize, GSMEM);
    cudaFuncSetAttribute(attn_hmma,
                         cudaFuncAttributeMaxDynamicSharedMemorySize, ASMEM);

    // 0) split inputs to (hi, lo) bf16
    {
        int n4 = MTOT * EMB / 4;
        split_kernel<<<n4 / 256, 256>>>((const float4*)x, (uint2*)x_h, (uint2*)x_l, n4);
        n4 = C3 * EMB / 4;
        split_kernel<<<n4 / 256, 256>>>((const float4*)w_attn, (uint2*)wa_h, (uint2*)wa_l, n4);
        n4 = EMB * EMB / 4;
        split_kernel<<<n4 / 256, 256>>>((const float4*)w_proj, (uint2*)wp_h, (uint2*)wp_l, n4);
    }

    // 1) qkv = x @ w_attn^T + b_attn, written directly as split bf16
    {
        dim3 grid(C3 / 128, MTOT / 128);
        gemm_hmma<true><<<grid, 256, GSMEM>>>(x_h, x_l, wa_h, wa_l, b_attn,
                                              nullptr, qkv_h, qkv_l,
                                              MTOT, C3, EMB);
    }

    // 2) HMMA flash attention -> split bf16 y
    {
        dim3 grid(SEQ / 128, HEADS, BATCH);
        attn_hmma<<<grid, 256, ASMEM>>>(qkv_h, qkv_l, y_h, y_l);
    }

    // 3) out = y @ w_proj^T + b_proj (fp32 out)
    {
        dim3 grid(EMB / 128, MTOT / 128);
        gemm_hmma<false><<<grid, 256, GSMEM>>>(y_h, y_l, wp_h, wp_l, b_proj,
                                               out, nullptr, nullptr,
                                               MTOT, EMB, EMB);
    }
}